// round 7
// baseline (speedup 1.0000x reference)
#include <cuda_runtime.h>
#include <cstdint>

#define BATCHES 16
#define NPTS    65536
#define NSAMP   2048
#define TPB     1024
#define GRPS    16                 // groups of 4 points per thread: 16*4*1024 = 65536

__global__ void __launch_bounds__(TPB, 1)
fps_simple(const float* __restrict__ points, float* __restrict__ out)
{
    const int tid  = threadIdx.x;
    const int warp = tid >> 5;
    const int lane = tid & 31;
    const int batch = blockIdx.x;
    const float* bp = points + (size_t)batch * NPTS * 3;

    __shared__ float s_v[TPB / 32];
    __shared__ int   s_i[TPB / 32];
    __shared__ int   s_widx;

    // per-thread min_dist for 64 owned points (local memory)
    float md[GRPS * 4];
    #pragma unroll
    for (int k = 0; k < GRPS * 4; k++) md[k] = 1e10f;

    // seed centroid = point 0
    float cx = __ldg(bp), cy = __ldg(bp + 1), cz = __ldg(bp + 2);
    if (tid == 0) out[batch * NSAMP] = 0.0f;

    for (int m = 1; m < NSAMP; m++) {
        float bv = -1.0f;
        int   bi = 0;

        #pragma unroll
        for (int j = 0; j < GRPS; j++) {
            const int g = tid + j * TPB;          // group id, 4 points per group
            // 3x float4 = 48B = coords of points 4g..4g+3 (48g % 16 == 0)
            const float4 f0 = __ldg(reinterpret_cast<const float4*>(bp + 12 * g));
            const float4 f1 = __ldg(reinterpret_cast<const float4*>(bp + 12 * g + 4));
            const float4 f2 = __ldg(reinterpret_cast<const float4*>(bp + 12 * g + 8));

            const float qx[4] = { f0.x, f0.w, f1.z, f2.y };
            const float qy[4] = { f0.y, f1.x, f1.w, f2.z };
            const float qz[4] = { f0.z, f1.y, f2.x, f2.w };

            #pragma unroll
            for (int q = 0; q < 4; q++) {
                // XLA:GPU fused lowering: d = fma(dz,dz, fma(dy,dy, dx*dx))
                float dx = __fsub_rn(qx[q], cx);
                float dy = __fsub_rn(qy[q], cy);
                float dz = __fsub_rn(qz[q], cz);
                float d  = fmaf(dz, dz, fmaf(dy, dy, __fmul_rn(dx, dx)));
                float nm = fminf(md[j * 4 + q], d);
                md[j * 4 + q] = nm;
                // strict > keeps FIRST occurrence; owned indices ascend with (j,q)
                if (nm > bv) { bv = nm; bi = 4 * g + q; }
            }
        }

        // ---- warp argmax: (value desc, index asc) ----
        #pragma unroll
        for (int off = 16; off > 0; off >>= 1) {
            float ov = __shfl_xor_sync(0xffffffffu, bv, off);
            int   oi = __shfl_xor_sync(0xffffffffu, bi, off);
            if (ov > bv || (ov == bv && oi < bi)) { bv = ov; bi = oi; }
        }
        if (lane == 0) { s_v[warp] = bv; s_i[warp] = bi; }
        __syncthreads();

        // ---- block argmax (warp 0) ----
        if (warp == 0) {
            bv = s_v[lane];
            bi = s_i[lane];
            #pragma unroll
            for (int off = 16; off > 0; off >>= 1) {
                float ov = __shfl_xor_sync(0xffffffffu, bv, off);
                int   oi = __shfl_xor_sync(0xffffffffu, bi, off);
                if (ov > bv || (ov == bv && oi < bi)) { bv = ov; bi = oi; }
            }
            if (lane == 0) s_widx = bi;
        }
        __syncthreads();

        const int widx = s_widx;
        cx = __ldg(bp + 3 * widx);
        cy = __ldg(bp + 3 * widx + 1);
        cz = __ldg(bp + 3 * widx + 2);
        if (tid == 0) out[batch * NSAMP + m] = (float)widx;
        // s_widx / s_v / s_i for iter m are consumed before the first
        // __syncthreads() of iter m+1, which precedes their overwrite.
    }
}

extern "C" void kernel_launch(void* const* d_in, const int* in_sizes, int n_in,
                              void* d_out, int out_size) {
    const float* points = (const float*)d_in[0];
    float* out = (float*)d_out;
    fps_simple<<<BATCHES, TPB>>>(points, out);
}

// round 10
// speedup vs baseline: 3.6525x; 3.6525x over previous
#include <cuda_runtime.h>
#include <cstdint>

#define BATCHES 16
#define NPTS    65536
#define NSAMP   2048
#define CPB     8                  // CTAs per cluster (= per batch)
#define TPB     1024
#define PPT     8                  // points per thread
#define SLAB    (NPTS / CPB)       // 8192 points per CTA

__device__ __forceinline__ uint32_t smem_u32(const void* p) {
    return (uint32_t)__cvta_generic_to_shared(p);
}
__device__ __forceinline__ void st_remote_u64(uint32_t laddr, uint32_t rank,
                                              unsigned long long v) {
    uint32_t raddr;
    asm volatile("mapa.shared::cluster.u32 %0, %1, %2;"
                 : "=r"(raddr) : "r"(laddr), "r"(rank));
    asm volatile("st.shared::cluster.u64 [%0], %1;"
                 :: "r"(raddr), "l"(v) : "memory");
}
__device__ __forceinline__ void cluster_barrier() {
    asm volatile("barrier.cluster.arrive.aligned;" ::: "memory");
    asm volatile("barrier.cluster.wait.aligned;"   ::: "memory");
}

__global__ void __launch_bounds__(TPB, 1) __cluster_dims__(CPB, 1, 1)
fps_cluster(const float* __restrict__ points, float* __restrict__ out)
{
    const int tid  = threadIdx.x;
    const int warp = tid >> 5;
    const int lane = tid & 31;
    uint32_t rank;
    asm("mov.u32 %0, %%cluster_ctarank;" : "=r"(rank));
    const int batch = blockIdx.x / CPB;
    const float* bp = points + (size_t)batch * NPTS * 3;

    __shared__ unsigned long long warp_keys[TPB / 32];
    __shared__ unsigned long long cta_keys[2][CPB];

    // ---- register-resident points + min_dist (bit-proven R7 numeric core) ----
    float px[PPT], py[PPT], pz[PPT], md[PPT];
    const int base = (int)rank * SLAB + tid;      // owned indices ascend with k
    #pragma unroll
    for (int k = 0; k < PPT; k++) {
        int i = base + k * TPB;
        px[k] = __ldg(bp + 3 * i);
        py[k] = __ldg(bp + 3 * i + 1);
        pz[k] = __ldg(bp + 3 * i + 2);
        md[k] = 1e10f;
    }

    float cx = __ldg(bp), cy = __ldg(bp + 1), cz = __ldg(bp + 2);
    if (rank == 0 && tid == 0) out[batch * NSAMP] = 0.0f;

    cluster_barrier();   // all cluster CTAs resident before first DSMEM store

    for (int m = 1; m < NSAMP; m++) {
        // ---- distance update: validated d = fma(dz,dz, fma(dy,dy, dx*dx)) ----
        float bv = -1.0f;
        int   bi = 0;
        #pragma unroll
        for (int k = 0; k < PPT; k++) {
            float dx = __fsub_rn(px[k], cx);
            float dy = __fsub_rn(py[k], cy);
            float dz = __fsub_rn(pz[k], cz);
            float d  = fmaf(dz, dz, fmaf(dy, dy, __fmul_rn(dx, dx)));
            float nm = fminf(md[k], d);
            md[k] = nm;
            // strict > keeps FIRST occurrence; owned indices ascend with k
            if (nm > bv) { bv = nm; bi = base + k * TPB; }
        }

        // pack (monotone for v>=0): high=value bits, low=~idx.
        // u64 max == (value desc, idx asc) — validated comparator semantics.
        unsigned long long key =
            ((unsigned long long)__float_as_uint(bv) << 32)
            | (unsigned int)(~(unsigned int)bi);

        // ---- warp reduce (all lanes end with the max) ----
        #pragma unroll
        for (int off = 16; off > 0; off >>= 1) {
            unsigned long long o = __shfl_xor_sync(0xffffffffu, key, off);
            if (o > key) key = o;
        }
        if (lane == 0) warp_keys[warp] = key;
        __syncthreads();

        // ---- block reduce (warp 0) + DSMEM broadcast of this CTA's key ----
        if (warp == 0) {
            key = warp_keys[lane];
            #pragma unroll
            for (int off = 16; off > 0; off >>= 1) {
                unsigned long long o = __shfl_xor_sync(0xffffffffu, key, off);
                if (o > key) key = o;
            }
            // every lane holds the block max; lanes 0..7 deliver it to
            // CTA `lane`'s smem slot [m&1][rank]
            if (lane < CPB)
                st_remote_u64(smem_u32(&cta_keys[m & 1][rank]), (uint32_t)lane, key);
        }

        // HW release/acquire: orders all 8 CTAs' DSMEM stores before all reads
        cluster_barrier();

        // ---- every thread reduces the 8 CTA keys identically ----
        unsigned long long best = cta_keys[m & 1][0];
        #pragma unroll
        for (int r = 1; r < CPB; r++) {
            unsigned long long o = cta_keys[m & 1][r];
            if (o > best) best = o;
        }
        const int widx = (int)(~(unsigned int)best);

        cx = __ldg(bp + 3 * widx);
        cy = __ldg(bp + 3 * widx + 1);
        cz = __ldg(bp + 3 * widx + 2);
        if (rank == 0 && tid == 0) out[batch * NSAMP + m] = (float)widx;
        // warp_keys reuse in iter m+1 is separated by its __syncthreads();
        // cta_keys slot reuse (m+2) is separated by the m+1 cluster barrier.
    }
}

extern "C" void kernel_launch(void* const* d_in, const int* in_sizes, int n_in,
                              void* d_out, int out_size) {
    const float* points = (const float*)d_in[0];
    float* out = (float*)d_out;

    cudaLaunchConfig_t cfg = {};
    cfg.gridDim  = dim3(BATCHES * CPB, 1, 1);
    cfg.blockDim = dim3(TPB, 1, 1);
    cfg.dynamicSmemBytes = 0;
    cfg.stream = 0;

    cudaLaunchAttribute attrs[1];
    attrs[0].id = cudaLaunchAttributeClusterDimension;
    attrs[0].val.clusterDim.x = CPB;
    attrs[0].val.clusterDim.y = 1;
    attrs[0].val.clusterDim.z = 1;
    cfg.attrs = attrs;
    cfg.numAttrs = 1;

    cudaLaunchKernelEx(&cfg, fps_cluster, points, out);
}